// round 15
// baseline (speedup 1.0000x reference)
#include <cuda_runtime.h>
#include <cuda_fp16.h>
#include <cstdint>

#define HDIM     128
#define NS       64
#define NRAYS    16384
#define NTHREADS 256

// ---- prep kernel smem (B tiles, ldmatrix-compatible swizzle-free pitch) ----
#define P_BH       0
#define P_BL       34816
#define SMEM_PREP  69632
#define B_PITCH_B  272     // bytes per row (136 halves) -> conflict-free ldmatrix

// ---- main kernel static smem layout (bytes) ----
#define M_B3    0       // 4 floats
#define M_B2    16      // 128 floats
#define M_W3    528     // 128 x float4 = 2048
#define M_O1    2576    // 128 floats
#define M_D1    3088    // 128 floats
#define M_WT    3600    // 2 floats + pad
#define M_PART  3632    // 2 warps x 4 floats
#define M_REND  3664    // 64 rows x 5 float4 = 5120
#define M_A     8784    // A tile: 64 samples x 272B = 17408
#define M_TOTAL (8784 + 17408)

#define REND_S  5       // float4 units per row (4 cg + 1 pad)

// B fragment arrays: [nt(16-col block) 0..7][ks 0..7][lane 0..31] uint4 = 32KB each
__device__ uint4 g_bfh[8 * 8 * 32];
__device__ uint4 g_bfl[8 * 8 * 32];

static __device__ __forceinline__ uint32_t smem_u32(const void* p) {
    uint32_t a;
    asm("{ .reg .u64 t; cvta.to.shared.u64 t, %1; cvt.u32.u64 %0, t; }" : "=r"(a) : "l"(p));
    return a;
}

static __device__ __forceinline__ float decode_scalar(const int* p) {
    int v = *p;
    if (v >= -1000000 && v <= 1000000) return (float)v;
    return __int_as_float(v);
}

#define MMA16816(D, A0, A1, A2, A3, B0, B1) \
    asm volatile("mma.sync.aligned.m16n8k16.row.col.f32.f16.f16.f32 " \
                 "{%0,%1,%2,%3}, {%4,%5,%6,%7}, {%8,%9}, {%0,%1,%2,%3};" \
                 : "+f"((D)[0]), "+f"((D)[1]), "+f"((D)[2]), "+f"((D)[3]) \
                 : "r"(A0), "r"(A1), "r"(A2), "r"(A3), "r"(B0), "r"(B1))

#define LDSM_X4(R0, R1, R2, R3, ADDR) \
    asm volatile("ldmatrix.sync.aligned.m8n8.x4.shared.b16 {%0,%1,%2,%3}, [%4];" \
                 : "=r"(R0), "=r"(R1), "=r"(R2), "=r"(R3) : "r"(ADDR))

// ---------------- prep: build B fragment arrays in global memory ----------------
__global__ void nerf_prep_kernel(const float* __restrict__ W2) {
    extern __shared__ char psm[];
    const uint32_t base = smem_u32(psm);
    const int tid = threadIdx.x;
    const int wid = tid >> 5;      // warp = nt block (8 warps, 8 nt blocks)
    const int lid = tid & 31;

    for (int i = tid; i < HDIM * HDIM; i += NTHREADS) {
        int k = i >> 7, n = i & 127;
        float w = W2[i];
        __half hh = __float2half_rn(w);
        __half hl = __float2half_rn(w - __half2float(hh));
        *(__half*)(psm + P_BH + n * B_PITCH_B + k * 2) = hh;
        *(__half*)(psm + P_BL + n * B_PITCH_B + k * 2) = hl;
    }
    __syncthreads();

    // identical ldmatrix mapping to the mainloop -> frag layout correct by construction
    const uint32_t lm_off = (uint32_t)(((lid & 7) + ((lid >> 4) & 1) * 8) * B_PITCH_B)
                          + (uint32_t)(((lid >> 3) & 1) * 16)
                          + (uint32_t)(wid * 16) * B_PITCH_B;
    const uint32_t hi = base + P_BH + lm_off;
    const uint32_t lo = base + P_BL + lm_off;

    #pragma unroll
    for (int ks = 0; ks < 8; ks++) {
        uint32_t b0, b1, b2, b3;
        LDSM_X4(b0, b1, b2, b3, hi + (uint32_t)(ks * 32));
        g_bfh[(wid * 8 + ks) * 32 + lid] = make_uint4(b0, b1, b2, b3);
        LDSM_X4(b0, b1, b2, b3, lo + (uint32_t)(ks * 32));
        g_bfl[(wid * 8 + ks) * 32 + lid] = make_uint4(b0, b1, b2, b3);
    }
}

// ---------------- main: persistent, 1 ray per CTA-iteration, 3 CTAs/SM ----------------
__global__ void __launch_bounds__(NTHREADS, 3)
nerf_fused_kernel(const float* __restrict__ origins, const float* __restrict__ dirs,
                  const float* __restrict__ W1, const float* __restrict__ b1,
                  const float* __restrict__ b2v, const float* __restrict__ W3,
                  const float* __restrict__ b3v,
                  const int* __restrict__ nearp, const int* __restrict__ farp,
                  float* __restrict__ out)
{
    __shared__ char smem[M_TOTAL];
    const uint32_t smem_base = smem_u32(smem);
    const int tid = threadIdx.x;
    const int wid = tid >> 5;
    const int lid = tid & 31;

    float*  b3s  = (float*)(smem + M_B3);
    float*  b2s  = (float*)(smem + M_B2);
    float*  o1s  = (float*)(smem + M_O1);
    float*  d1s  = (float*)(smem + M_D1);
    float*  wt   = (float*)(smem + M_WT);
    float*  part = (float*)(smem + M_PART);
    float4* rend = (float4*)(smem + M_REND);

    if (tid < HDIM) {
        b2s[tid] = b2v[tid];
        ((float4*)(smem + M_W3))[tid] = ((const float4*)W3)[tid];
    }
    if (tid < 4) b3s[tid] = b3v[tid];

    const float nearf = decode_scalar(nearp);
    const float farf  = decode_scalar(farp);
    const float delta = (farf - nearf) * (1.0f / (float)NS);

    // warp decomposition: rg = 32-row group (0..1), cg = 32-col group (0..3)
    const int tq = lid & 3;            // 0..3 (used in epilogue col mapping)
    const int q  = lid >> 2;           // 0..7
    const int rg = wid >> 2;           // 0..1
    const int cg = wid & 3;            // 0..3

    // A-tile ldmatrix lane address (row-major A fragments):
    // addr = base + (rowbase + (lid&15))*pitch + (lid>>4)*16  (+ ks*32 per k-step)
    const uint32_t a_lm = smem_base + M_A
        + (uint32_t)((rg * 32 + (lid & 15)) * B_PITCH_B)
        + (uint32_t)((lid >> 4) * 16);

    // A-pack phase constants: thread packs sample s = tid>>2, quarter qp = tid&3
    const int ps  = tid >> 2;          // 0..63
    const int qp  = tid & 3;           // 0..3 -> uint32 cols qp*16..+15
    const float pt = fmaf((float)ps + 0.5f, delta, nearf);

    __syncthreads();

    for (int ray = blockIdx.x; ray < NRAYS; ray += gridDim.x) {
        // ---- layer-1: o1 = o@W1 + b1, d1 = d@W1 (thread j = column, tid<128) ----
        if (tid < HDIM) {
            int j = tid;
            float w0 = W1[j], w1v = W1[HDIM + j], w2v = W1[2 * HDIM + j];
            float ox = origins[ray * 3 + 0], oy = origins[ray * 3 + 1], oz = origins[ray * 3 + 2];
            float dx = dirs[ray * 3 + 0],    dy = dirs[ray * 3 + 1],    dz = dirs[ray * 3 + 2];
            o1s[j] = fmaf(ox, w0, fmaf(oy, w1v, fmaf(oz, w2v, b1[j])));
            d1s[j] = fmaf(dx, w0, fmaf(dy, w1v, dz * w2v));
        }
        __syncthreads();

        // ---- A-pack (each half packed exactly once): A[s][k] = fp16(relu(o1+t*d1)) ----
        {
            const float2* o2 = (const float2*)o1s;
            const float2* d2 = (const float2*)d1s;
            uint32_t* arow = (uint32_t*)(smem + M_A + ps * B_PITCH_B) + qp * 16;
            #pragma unroll
            for (int i = 0; i < 16; i++) {
                const int jj = qp * 16 + i;
                float2 o = o2[jj], d = d2[jj];
                float h0 = fmaxf(fmaf(pt, d.x, o.x), 0.0f);
                float h1 = fmaxf(fmaf(pt, d.y, o.y), 0.0f);
                __half2 hh = __floats2half2_rn(h0, h1);
                arow[i] = *(uint32_t*)&hh;
            }
        }
        __syncthreads();

        // ---- layer-2 GEMM: warp tile m32 x n32, A from smem LDSM, B frags from L1 ----
        // acc[mf*16 + ntb*8 + half*4 + i]
        float acc[32];
        #pragma unroll
        for (int i = 0; i < 32; i++) acc[i] = 0.0f;

        #pragma unroll
        for (int ks = 0; ks < 8; ks++) {
            uint32_t a[2][4];
            #pragma unroll
            for (int mf = 0; mf < 2; mf++) {
                LDSM_X4(a[mf][0], a[mf][1], a[mf][2], a[mf][3],
                        a_lm + (uint32_t)(mf * 16 * B_PITCH_B) + (uint32_t)(ks * 32));
            }

            #pragma unroll
            for (int ntb = 0; ntb < 2; ntb++) {
                const int idx = (((cg * 2 + ntb) * 8 + ks) * 32) + lid;
                const uint4 bh = g_bfh[idx];
                const uint4 bl = g_bfl[idx];
                #pragma unroll
                for (int mf = 0; mf < 2; mf++) {
                    float* dA = acc + mf * 16 + ntb * 8;
                    float* dB = dA + 4;
                    MMA16816(dA, a[mf][0], a[mf][1], a[mf][2], a[mf][3], bh.x, bh.y);
                    MMA16816(dB, a[mf][0], a[mf][1], a[mf][2], a[mf][3], bh.z, bh.w);
                    MMA16816(dA, a[mf][0], a[mf][1], a[mf][2], a[mf][3], bl.x, bl.y);
                    MMA16816(dB, a[mf][0], a[mf][1], a[mf][2], a[mf][3], bl.z, bl.w);
                }
            }
        }

        // ---- epilogue: h2 = relu(D + b2); partial layer-3 over 32 cols; quad reduce ----
        #pragma unroll
        for (int mf = 0; mf < 2; mf++) {
            float pr0 = 0, pg0 = 0, pb0 = 0, ps0 = 0;
            float pr1 = 0, pg1 = 0, pb1 = 0, ps1 = 0;
            #pragma unroll
            for (int ntb = 0; ntb < 2; ntb++) {
                #pragma unroll
                for (int half = 0; half < 2; half++) {
                    const float* a4 = acc + mf * 16 + ntb * 8 + half * 4;
                    const int c0 = cg * 32 + ntb * 16 + half * 8 + 2 * tq;
                    const float bb0 = b2s[c0], bb1 = b2s[c0 + 1];
                    const float4 wA = *(const float4*)(smem + M_W3 + c0 * 16);
                    const float4 wB = *(const float4*)(smem + M_W3 + (c0 + 1) * 16);
                    float h00 = fmaxf(a4[0] + bb0, 0.0f);
                    float h01 = fmaxf(a4[1] + bb1, 0.0f);
                    float h10 = fmaxf(a4[2] + bb0, 0.0f);
                    float h11 = fmaxf(a4[3] + bb1, 0.0f);
                    pr0 = fmaf(h00, wA.x, fmaf(h01, wB.x, pr0));
                    pg0 = fmaf(h00, wA.y, fmaf(h01, wB.y, pg0));
                    pb0 = fmaf(h00, wA.z, fmaf(h01, wB.z, pb0));
                    ps0 = fmaf(h00, wA.w, fmaf(h01, wB.w, ps0));
                    pr1 = fmaf(h10, wA.x, fmaf(h11, wB.x, pr1));
                    pg1 = fmaf(h10, wA.y, fmaf(h11, wB.y, pg1));
                    pb1 = fmaf(h10, wA.z, fmaf(h11, wB.z, pb1));
                    ps1 = fmaf(h10, wA.w, fmaf(h11, wB.w, ps1));
                }
            }
            #pragma unroll
            for (int off = 1; off <= 2; off <<= 1) {
                pr0 += __shfl_xor_sync(0xffffffffu, pr0, off);
                pg0 += __shfl_xor_sync(0xffffffffu, pg0, off);
                pb0 += __shfl_xor_sync(0xffffffffu, pb0, off);
                ps0 += __shfl_xor_sync(0xffffffffu, ps0, off);
                pr1 += __shfl_xor_sync(0xffffffffu, pr1, off);
                pg1 += __shfl_xor_sync(0xffffffffu, pg1, off);
                pb1 += __shfl_xor_sync(0xffffffffu, pb1, off);
                ps1 += __shfl_xor_sync(0xffffffffu, ps1, off);
            }
            if (tq == 0) {
                const int row = rg * 32 + mf * 16 + q;   // 0..63 (sample)
                rend[row * REND_S + cg]       = make_float4(pr0, pg0, pb0, ps0);
                rend[(row + 8) * REND_S + cg] = make_float4(pr1, pg1, pb1, ps1);
            }
        }
        __syncthreads();

        // ---- volume rendering: 64 samples, exact log-space scan (tid<64) ----
        float cr = 0, cg2 = 0, cb = 0, sd = 0, x = 0;
        if (tid < 64) {
            float4 f0 = rend[tid * REND_S + 0];
            float4 f1 = rend[tid * REND_S + 1];
            float4 f2 = rend[tid * REND_S + 2];
            float4 f3 = rend[tid * REND_S + 3];
            cr  = f0.x + f1.x + f2.x + f3.x + b3s[0];
            cg2 = f0.y + f1.y + f2.y + f3.y + b3s[1];
            cb  = f0.z + f1.z + f2.z + f3.z + b3s[2];
            sd  = (f0.w + f1.w + f2.w + f3.w + b3s[3]) * delta;

            x = sd;
            #pragma unroll
            for (int off = 1; off < 32; off <<= 1) {
                float v = __shfl_up_sync(0xffffffffu, x, off);
                if (lid >= off) x += v;
            }
            if (lid == 31) wt[wid] = x;
        }
        __syncthreads();
        if (tid < 64) {
            float pre = x - sd;
            if (wid == 1) pre += wt[0];
            float w = __expf(-pre) - __expf(-(pre + sd));

            float wr = w * cr, wg = w * cg2, wb = w * cb;
            #pragma unroll
            for (int off = 16; off > 0; off >>= 1) {
                wr += __shfl_down_sync(0xffffffffu, wr, off);
                wg += __shfl_down_sync(0xffffffffu, wg, off);
                wb += __shfl_down_sync(0xffffffffu, wb, off);
            }
            if (lid == 0) {
                float* p = part + wid * 4;
                p[0] = wr; p[1] = wg; p[2] = wb;
            }
        }
        __syncthreads();
        if (tid == 0) {
            out[ray * 3 + 0] = part[0] + part[4];
            out[ray * 3 + 1] = part[1] + part[5];
            out[ray * 3 + 2] = part[2] + part[6];
        }
        // no trailing sync: o1s/A/rend/wt/part next written only after at least
        // one intervening __syncthreads in the next iteration.
    }
}

extern "C" void kernel_launch(void* const* d_in, const int* in_sizes, int n_in,
                              void* d_out, int out_size) {
    (void)in_sizes; (void)n_in; (void)out_size;
    const float* origins = (const float*)d_in[0];
    const float* dirs    = (const float*)d_in[1];
    const float* W1      = (const float*)d_in[2];
    const float* b1      = (const float*)d_in[3];
    const float* W2      = (const float*)d_in[4];
    const float* b2v     = (const float*)d_in[5];
    const float* W3      = (const float*)d_in[6];
    const float* b3v     = (const float*)d_in[7];
    const int*   nearp   = (const int*)d_in[8];
    const int*   farp    = (const int*)d_in[9];
    float* out = (float*)d_out;

    int sms = 0;
    cudaDeviceGetAttribute(&sms, cudaDevAttrMultiProcessorCount, 0);
    if (sms <= 0) sms = 148;

    cudaFuncSetAttribute(nerf_prep_kernel,
                         cudaFuncAttributeMaxDynamicSharedMemorySize, SMEM_PREP);
    nerf_prep_kernel<<<1, NTHREADS, SMEM_PREP>>>(W2);

    int grid = sms * 3;                 // persistent: 3 CTAs/SM
    if (grid > NRAYS) grid = NRAYS;
    nerf_fused_kernel<<<grid, NTHREADS>>>(
        origins, dirs, W1, b1, b2v, W3, b3v, nearp, farp, out);
}

// round 16
// speedup vs baseline: 1.4300x; 1.4300x over previous
#include <cuda_runtime.h>
#include <cuda_fp16.h>
#include <cstdint>

#define HDIM     128
#define NS       64
#define NRAYS    16384
#define NTILES   8192      // 2 rays / 128 samples per tile
#define NTHREADS 256

// ---- prep kernel smem (B tiles, ldmatrix-compatible pitch) ----
#define P_BH       0
#define P_BL       34816
#define SMEM_PREP  69632
#define B_PITCH_B  272     // bytes per row (136 halves) -> conflict-free ldmatrix

// ---- main kernel dynamic smem layout (bytes) ----
#define M_B3    0       // 4 floats
#define M_B2    16      // 128 floats
#define M_W3    528     // 128 x float4 = 2048
#define M_O1    2576    // 2*128 floats
#define M_D1    3600    // 2*128 floats
#define M_WT    4624    // 4 floats
#define M_PART  4640    // 4 warps x 4 floats
#define M_REND  4736    // 128 rows x 9 float4 (stride 144B) = 18432
#define M_A     23168   // A tile: 128 samples x 272B = 34816
#define M_TOTAL (23168 + 34816)

#define REND_S  9       // float4 units per row (8 warp slots + 1 pad)

// B fragment arrays: [nt(16-col block) 0..7][ks 0..7][lane 0..31] uint4 = 32KB each
__device__ uint4 g_bfh[8 * 8 * 32];
__device__ uint4 g_bfl[8 * 8 * 32];

static __device__ __forceinline__ uint32_t smem_u32(const void* p) {
    uint32_t a;
    asm("{ .reg .u64 t; cvta.to.shared.u64 t, %1; cvt.u32.u64 %0, t; }" : "=r"(a) : "l"(p));
    return a;
}

static __device__ __forceinline__ float decode_scalar(const int* p) {
    int v = *p;
    if (v >= -1000000 && v <= 1000000) return (float)v;
    return __int_as_float(v);
}

#define MMA16816(D, A0, A1, A2, A3, B0, B1) \
    asm volatile("mma.sync.aligned.m16n8k16.row.col.f32.f16.f16.f32 " \
                 "{%0,%1,%2,%3}, {%4,%5,%6,%7}, {%8,%9}, {%0,%1,%2,%3};" \
                 : "+f"((D)[0]), "+f"((D)[1]), "+f"((D)[2]), "+f"((D)[3]) \
                 : "r"(A0), "r"(A1), "r"(A2), "r"(A3), "r"(B0), "r"(B1))

#define LDSM_X4(R0, R1, R2, R3, ADDR) \
    asm volatile("ldmatrix.sync.aligned.m8n8.x4.shared.b16 {%0,%1,%2,%3}, [%4];" \
                 : "=r"(R0), "=r"(R1), "=r"(R2), "=r"(R3) : "r"(ADDR))

// ---------------- prep: build B fragment arrays in global memory ----------------
__global__ void nerf_prep_kernel(const float* __restrict__ W2) {
    extern __shared__ char psm[];
    const uint32_t base = smem_u32(psm);
    const int tid = threadIdx.x;
    const int wid = tid >> 5;      // warp = nt block (8 warps, 8 nt blocks)
    const int lid = tid & 31;

    for (int i = tid; i < HDIM * HDIM; i += NTHREADS) {
        int k = i >> 7, n = i & 127;
        float w = W2[i];
        __half hh = __float2half_rn(w);
        __half hl = __float2half_rn(w - __half2float(hh));
        *(__half*)(psm + P_BH + n * B_PITCH_B + k * 2) = hh;
        *(__half*)(psm + P_BL + n * B_PITCH_B + k * 2) = hl;
    }
    __syncthreads();

    // identical ldmatrix mapping to the mainloop consumer -> layout correct by construction
    const uint32_t lm_off = (uint32_t)(((lid & 7) + ((lid >> 4) & 1) * 8) * B_PITCH_B)
                          + (uint32_t)(((lid >> 3) & 1) * 16)
                          + (uint32_t)(wid * 16) * B_PITCH_B;
    const uint32_t hi = base + P_BH + lm_off;
    const uint32_t lo = base + P_BL + lm_off;

    #pragma unroll
    for (int ks = 0; ks < 8; ks++) {
        uint32_t b0, b1, b2, b3;
        LDSM_X4(b0, b1, b2, b3, hi + (uint32_t)(ks * 32));
        g_bfh[(wid * 8 + ks) * 32 + lid] = make_uint4(b0, b1, b2, b3);
        LDSM_X4(b0, b1, b2, b3, lo + (uint32_t)(ks * 32));
        g_bfl[(wid * 8 + ks) * 32 + lid] = make_uint4(b0, b1, b2, b3);
    }
}

// ---------------- main: persistent, 2 rays (128 samples) per CTA-iteration ----------------
__global__ void __launch_bounds__(NTHREADS, 2)
nerf_fused_kernel(const float* __restrict__ origins, const float* __restrict__ dirs,
                  const float* __restrict__ W1, const float* __restrict__ b1,
                  const float* __restrict__ b2v, const float* __restrict__ W3,
                  const float* __restrict__ b3v,
                  const int* __restrict__ nearp, const int* __restrict__ farp,
                  float* __restrict__ out)
{
    extern __shared__ char smem[];
    const uint32_t smem_base = smem_u32(smem);
    const int tid = threadIdx.x;
    const int wid = tid >> 5;          // 0..7 = n-block owned by this warp
    const int lid = tid & 31;

    float*  b3s  = (float*)(smem + M_B3);
    float*  b2s  = (float*)(smem + M_B2);
    float*  o1s  = (float*)(smem + M_O1);
    float*  d1s  = (float*)(smem + M_D1);
    float*  wt   = (float*)(smem + M_WT);
    float*  part = (float*)(smem + M_PART);
    float4* rend = (float4*)(smem + M_REND);

    if (tid < HDIM) {
        b2s[tid] = b2v[tid];
        ((float4*)(smem + M_W3))[tid] = ((const float4*)W3)[tid];
    }
    if (tid < 4) b3s[tid] = b3v[tid];

    // ---- preload this warp's B fragments into registers (persistent) ----
    uint4 Bh[8], Bl[8];
    #pragma unroll
    for (int ks = 0; ks < 8; ks++) {
        Bh[ks] = g_bfh[(wid * 8 + ks) * 32 + lid];
        Bl[ks] = g_bfl[(wid * 8 + ks) * 32 + lid];
    }

    const float nearf = decode_scalar(nearp);
    const float farf  = decode_scalar(farp);
    const float delta = (farf - nearf) * (1.0f / (float)NS);

    const int tq = lid & 3;            // col quad
    const int q  = lid >> 2;           // row-in-frag 0..7

    // A ldmatrix lane address (row-major A fragments; validated mapping)
    const uint32_t a_lm = smem_base + M_A
        + (uint32_t)((lid & 15) * B_PITCH_B)
        + (uint32_t)((lid >> 4) * 16);

    // A-pack constants: thread packs sample s_pk (row), half hsel (32 uint32 cols)
    const int s_pk  = tid & 127;
    const int hsel  = tid >> 7;
    const float t_pk = fmaf((float)(s_pk & 63) + 0.5f, delta, nearf);
    uint4* arow = (uint4*)(smem + M_A + s_pk * B_PITCH_B + hsel * 128);

    __syncthreads();

    for (int tile = blockIdx.x; tile < NTILES; tile += gridDim.x) {
        // ---- layer-1 for 2 rays: o1 = o@W1 + b1, d1 = d@W1 (thread j = column) ----
        if (tid < HDIM) {
            int j = tid;
            float w0 = W1[j], w1v = W1[HDIM + j], w2v = W1[2 * HDIM + j], bb = b1[j];
            #pragma unroll
            for (int r = 0; r < 2; r++) {
                int ray = tile * 2 + r;
                float ox = origins[ray * 3 + 0], oy = origins[ray * 3 + 1], oz = origins[ray * 3 + 2];
                float dx = dirs[ray * 3 + 0],    dy = dirs[ray * 3 + 1],    dz = dirs[ray * 3 + 2];
                o1s[r * HDIM + j] = fmaf(ox, w0, fmaf(oy, w1v, fmaf(oz, w2v, bb)));
                d1s[r * HDIM + j] = fmaf(dx, w0, fmaf(dy, w1v, dz * w2v));
            }
        }
        __syncthreads();

        // ---- A-pack (each half packed once; STS.128 conflict-free by row mapping) ----
        {
            const float2* o2 = (const float2*)(o1s + (s_pk >> 6) * HDIM);
            const float2* d2 = (const float2*)(d1s + (s_pk >> 6) * HDIM);
            #pragma unroll
            for (int i4 = 0; i4 < 8; i4++) {
                uint32_t v[4];
                #pragma unroll
                for (int j = 0; j < 4; j++) {
                    const int jj = hsel * 32 + i4 * 4 + j;
                    float2 o = o2[jj], d = d2[jj];
                    float h0 = fmaxf(fmaf(t_pk, d.x, o.x), 0.0f);
                    float h1 = fmaxf(fmaf(t_pk, d.y, o.y), 0.0f);
                    __half2 hh = __floats2half2_rn(h0, h1);
                    v[j] = *(uint32_t*)&hh;
                }
                arow[i4] = make_uint4(v[0], v[1], v[2], v[3]);
            }
        }
        __syncthreads();

        // ---- mainloop: warp sweeps 8 row-blocks x n16 (B resident in registers) ----
        for (int rb = 0; rb < 8; rb++) {
            const uint32_t a_rb = a_lm + (uint32_t)(rb * 16 * B_PITCH_B);
            float acc[8];
            #pragma unroll
            for (int i = 0; i < 8; i++) acc[i] = 0.0f;

            #pragma unroll
            for (int ks = 0; ks < 8; ks++) {
                uint32_t a0, a1, a2, a3;
                LDSM_X4(a0, a1, a2, a3, a_rb + (uint32_t)(ks * 32));
                MMA16816(acc,     a0, a1, a2, a3, Bh[ks].x, Bh[ks].y);
                MMA16816(acc + 4, a0, a1, a2, a3, Bh[ks].z, Bh[ks].w);
                MMA16816(acc,     a0, a1, a2, a3, Bl[ks].x, Bl[ks].y);
                MMA16816(acc + 4, a0, a1, a2, a3, Bl[ks].z, Bl[ks].w);
            }

            // ---- per-rb epilogue: relu(D+b2), partial layer-3 over 16 cols, quad reduce ----
            const int c0 = wid * 16 + 2 * tq;       // n8lo pair
            const int c1 = c0 + 8;                  // n8hi pair
            const float bb0 = b2s[c0], bb1 = b2s[c0 + 1];
            const float bb2 = b2s[c1], bb3 = b2s[c1 + 1];
            const float4 w0 = *(const float4*)(smem + M_W3 + c0 * 16);
            const float4 w1 = *(const float4*)(smem + M_W3 + (c0 + 1) * 16);
            const float4 w2 = *(const float4*)(smem + M_W3 + c1 * 16);
            const float4 w3 = *(const float4*)(smem + M_W3 + (c1 + 1) * 16);

            float h00 = fmaxf(acc[0] + bb0, 0.0f), h01 = fmaxf(acc[1] + bb1, 0.0f);
            float h10 = fmaxf(acc[2] + bb0, 0.0f), h11 = fmaxf(acc[3] + bb1, 0.0f);
            float g00 = fmaxf(acc[4] + bb2, 0.0f), g01 = fmaxf(acc[5] + bb3, 0.0f);
            float g10 = fmaxf(acc[6] + bb2, 0.0f), g11 = fmaxf(acc[7] + bb3, 0.0f);

            float pr0 = fmaf(h00, w0.x, fmaf(h01, w1.x, fmaf(g00, w2.x, g01 * w3.x)));
            float pg0 = fmaf(h00, w0.y, fmaf(h01, w1.y, fmaf(g00, w2.y, g01 * w3.y)));
            float pb0 = fmaf(h00, w0.z, fmaf(h01, w1.z, fmaf(g00, w2.z, g01 * w3.z)));
            float ps0 = fmaf(h00, w0.w, fmaf(h01, w1.w, fmaf(g00, w2.w, g01 * w3.w)));
            float pr1 = fmaf(h10, w0.x, fmaf(h11, w1.x, fmaf(g10, w2.x, g11 * w3.x)));
            float pg1 = fmaf(h10, w0.y, fmaf(h11, w1.y, fmaf(g10, w2.y, g11 * w3.y)));
            float pb1 = fmaf(h10, w0.z, fmaf(h11, w1.z, fmaf(g10, w2.z, g11 * w3.z)));
            float ps1 = fmaf(h10, w0.w, fmaf(h11, w1.w, fmaf(g10, w2.w, g11 * w3.w)));

            #pragma unroll
            for (int off = 1; off <= 2; off <<= 1) {
                pr0 += __shfl_xor_sync(0xffffffffu, pr0, off);
                pg0 += __shfl_xor_sync(0xffffffffu, pg0, off);
                pb0 += __shfl_xor_sync(0xffffffffu, pb0, off);
                ps0 += __shfl_xor_sync(0xffffffffu, ps0, off);
                pr1 += __shfl_xor_sync(0xffffffffu, pr1, off);
                pg1 += __shfl_xor_sync(0xffffffffu, pg1, off);
                pb1 += __shfl_xor_sync(0xffffffffu, pb1, off);
                ps1 += __shfl_xor_sync(0xffffffffu, ps1, off);
            }
            if (tq == 0) {
                const int row = rb * 16 + q;        // 0..127
                rend[row * REND_S + wid]       = make_float4(pr0, pg0, pb0, ps0);
                rend[(row + 8) * REND_S + wid] = make_float4(pr1, pg1, pb1, ps1);
            }
        }
        __syncthreads();

        // ---- volume rendering: 2 rays, exact log-space scan (thread = sample) ----
        float cr = 0, cg = 0, cb = 0, sd = 0, x = 0;
        if (tid < 128) {
            float4 f = rend[tid * REND_S + 0];
            #pragma unroll
            for (int w = 1; w < 8; w++) {
                float4 g = rend[tid * REND_S + w];
                f.x += g.x; f.y += g.y; f.z += g.z; f.w += g.w;
            }
            cr = f.x + b3s[0]; cg = f.y + b3s[1]; cb = f.z + b3s[2];
            sd = (f.w + b3s[3]) * delta;

            x = sd;
            #pragma unroll
            for (int off = 1; off < 32; off <<= 1) {
                float v = __shfl_up_sync(0xffffffffu, x, off);
                if (lid >= off) x += v;
            }
            if (lid == 31) wt[wid] = x;
        }
        __syncthreads();
        if (tid < 128) {
            float pre = x - sd;
            if (wid & 1) pre += wt[wid & ~1];
            float w = __expf(-pre) - __expf(-(pre + sd));

            float wr = w * cr, wg = w * cg, wb = w * cb;
            #pragma unroll
            for (int off = 16; off > 0; off >>= 1) {
                wr += __shfl_down_sync(0xffffffffu, wr, off);
                wg += __shfl_down_sync(0xffffffffu, wg, off);
                wb += __shfl_down_sync(0xffffffffu, wb, off);
            }
            if (lid == 0) {
                float* p = part + wid * 4;
                p[0] = wr; p[1] = wg; p[2] = wb;
            }
        }
        __syncthreads();
        if (tid < 2) {
            const float* p0 = part + tid * 8;   // warps {2t, 2t+1}
            int ray = tile * 2 + tid;
            out[ray * 3 + 0] = p0[0] + p0[4];
            out[ray * 3 + 1] = p0[1] + p0[5];
            out[ray * 3 + 2] = p0[2] + p0[6];
        }
        // no trailing sync: o1s/A/rend/wt/part next written only after at least
        // one intervening __syncthreads in the next iteration.
    }
}

extern "C" void kernel_launch(void* const* d_in, const int* in_sizes, int n_in,
                              void* d_out, int out_size) {
    (void)in_sizes; (void)n_in; (void)out_size;
    const float* origins = (const float*)d_in[0];
    const float* dirs    = (const float*)d_in[1];
    const float* W1      = (const float*)d_in[2];
    const float* b1      = (const float*)d_in[3];
    const float* W2      = (const float*)d_in[4];
    const float* b2v     = (const float*)d_in[5];
    const float* W3      = (const float*)d_in[6];
    const float* b3v     = (const float*)d_in[7];
    const int*   nearp   = (const int*)d_in[8];
    const int*   farp    = (const int*)d_in[9];
    float* out = (float*)d_out;

    int sms = 0;
    cudaDeviceGetAttribute(&sms, cudaDevAttrMultiProcessorCount, 0);
    if (sms <= 0) sms = 148;

    cudaFuncSetAttribute(nerf_prep_kernel,
                         cudaFuncAttributeMaxDynamicSharedMemorySize, SMEM_PREP);
    nerf_prep_kernel<<<1, NTHREADS, SMEM_PREP>>>(W2);

    cudaFuncSetAttribute(nerf_fused_kernel,
                         cudaFuncAttributeMaxDynamicSharedMemorySize, M_TOTAL);
    int grid = sms * 2;                 // persistent: 2 CTAs/SM
    if (grid > NTILES) grid = NTILES;
    nerf_fused_kernel<<<grid, NTHREADS, M_TOTAL>>>(
        origins, dirs, W1, b1, b2v, W3, b3v, nearp, farp, out);
}

// round 17
// speedup vs baseline: 1.6566x; 1.1584x over previous
#include <cuda_runtime.h>
#include <cuda_fp16.h>
#include <cstdint>

#define HDIM     128
#define NS       64
#define NRAYS    16384
#define NTILES   8192      // 2 rays / 128 samples per tile
#define NTHREADS 256

// ---- prep kernel smem (B tiles, ldmatrix-compatible pitch) ----
#define P_BH       0
#define P_BL       34816
#define SMEM_PREP  69632
#define B_PITCH_B  272     // bytes per row (136 halves) -> conflict-free ldmatrix

// ---- main kernel dynamic smem layout (bytes) ----
#define M_B3    0       // 4 floats
#define M_O1    16      // 2*128 floats
#define M_D1    1040    // 2*128 floats
#define M_WT    2064    // 4 floats
#define M_PART  2080    // 4 warps x 4 floats
#define M_REND  2144    // 128 rows x 9 float4 (stride 144B) = 18432
#define M_A     20576   // A tile: 128 samples x 272B = 34816
#define M_TOTAL (20576 + 34816)

#define REND_S  9       // float4 units per row (8 warp slots + 1 pad)

// B fragment arrays: [nt 0..7][ks 0..7][lane 0..31] uint4 = 32KB each
__device__ uint4 g_bfh[8 * 8 * 32];
__device__ uint4 g_bfl[8 * 8 * 32];
// W3 B-fragments for the fused layer-3 MMA: [nt 0..7][lane 0..31]
__device__ uint2 g_w3h[8 * 32];
__device__ uint2 g_w3l[8 * 32];

static __device__ __forceinline__ uint32_t smem_u32(const void* p) {
    uint32_t a;
    asm("{ .reg .u64 t; cvta.to.shared.u64 t, %1; cvt.u32.u64 %0, t; }" : "=r"(a) : "l"(p));
    return a;
}

static __device__ __forceinline__ float decode_scalar(const int* p) {
    int v = *p;
    if (v >= -1000000 && v <= 1000000) return (float)v;
    return __int_as_float(v);
}

static __device__ __forceinline__ uint32_t pack2h(float a, float b) {
    __half2 h = __floats2half2_rn(a, b);
    return *(uint32_t*)&h;
}

#define MMA16816(D, A0, A1, A2, A3, B0, B1) \
    asm volatile("mma.sync.aligned.m16n8k16.row.col.f32.f16.f16.f32 " \
                 "{%0,%1,%2,%3}, {%4,%5,%6,%7}, {%8,%9}, {%0,%1,%2,%3};" \
                 : "+f"((D)[0]), "+f"((D)[1]), "+f"((D)[2]), "+f"((D)[3]) \
                 : "r"(A0), "r"(A1), "r"(A2), "r"(A3), "r"(B0), "r"(B1))

#define LDSM_X4(R0, R1, R2, R3, ADDR) \
    asm volatile("ldmatrix.sync.aligned.m8n8.x4.shared.b16 {%0,%1,%2,%3}, [%4];" \
                 : "=r"(R0), "=r"(R1), "=r"(R2), "=r"(R3) : "r"(ADDR))

// ---------------- prep: build B fragments + W3 fragments in global memory ----------------
__global__ void nerf_prep_kernel(const float* __restrict__ W2, const float* __restrict__ W3) {
    extern __shared__ char psm[];
    const uint32_t base = smem_u32(psm);
    const int tid = threadIdx.x;
    const int wid = tid >> 5;      // warp = nt block
    const int lid = tid & 31;
    const int q  = lid >> 2;
    const int tq = lid & 3;

    for (int i = tid; i < HDIM * HDIM; i += NTHREADS) {
        int k = i >> 7, n = i & 127;
        float w = W2[i];
        __half hh = __float2half_rn(w);
        __half hl = __float2half_rn(w - __half2float(hh));
        *(__half*)(psm + P_BH + n * B_PITCH_B + k * 2) = hh;
        *(__half*)(psm + P_BL + n * B_PITCH_B + k * 2) = hl;
    }
    __syncthreads();

    // identical ldmatrix mapping to the mainloop consumer -> layout correct by construction
    const uint32_t lm_off = (uint32_t)(((lid & 7) + ((lid >> 4) & 1) * 8) * B_PITCH_B)
                          + (uint32_t)(((lid >> 3) & 1) * 16)
                          + (uint32_t)(wid * 16) * B_PITCH_B;
    const uint32_t hi = base + P_BH + lm_off;
    const uint32_t lo = base + P_BL + lm_off;

    #pragma unroll
    for (int ks = 0; ks < 8; ks++) {
        uint32_t b0, b1, b2, b3;
        LDSM_X4(b0, b1, b2, b3, hi + (uint32_t)(ks * 32));
        g_bfh[(wid * 8 + ks) * 32 + lid] = make_uint4(b0, b1, b2, b3);
        LDSM_X4(b0, b1, b2, b3, lo + (uint32_t)(ks * 32));
        g_bfl[(wid * 8 + ks) * 32 + lid] = make_uint4(b0, b1, b2, b3);
    }

    // W3 B-fragments (m16n8k16, col-major B):
    // lane holds b0 = {B[2tq][q], B[2tq+1][q]}, b1 = {B[2tq+8][q], B[2tq+9][q]}
    // where B[k][n] = W3[wid*16 + k][n] for n<4, else 0.  W3 is [128][4] row-major.
    {
        float v00 = 0, v01 = 0, v10 = 0, v11 = 0;
        if (q < 4) {
            v00 = W3[(wid * 16 + 2 * tq) * 4 + q];
            v01 = W3[(wid * 16 + 2 * tq + 1) * 4 + q];
            v10 = W3[(wid * 16 + 2 * tq + 8) * 4 + q];
            v11 = W3[(wid * 16 + 2 * tq + 9) * 4 + q];
        }
        __half h00 = __float2half_rn(v00), h01 = __float2half_rn(v01);
        __half h10 = __float2half_rn(v10), h11 = __float2half_rn(v11);
        g_w3h[wid * 32 + lid] = make_uint2(pack2h(v00, v01) * 0u + (((uint32_t)*(uint16_t*)&h01) << 16 | (uint32_t)*(uint16_t*)&h00),
                                           (((uint32_t)*(uint16_t*)&h11) << 16 | (uint32_t)*(uint16_t*)&h10));
        float r00 = v00 - __half2float(h00), r01 = v01 - __half2float(h01);
        float r10 = v10 - __half2float(h10), r11 = v11 - __half2float(h11);
        g_w3l[wid * 32 + lid] = make_uint2(pack2h(r00, r01), pack2h(r10, r11));
    }
}

// ---------------- main: persistent, 2 rays (128 samples) per CTA-iteration ----------------
__global__ void __launch_bounds__(NTHREADS, 2)
nerf_fused_kernel(const float* __restrict__ origins, const float* __restrict__ dirs,
                  const float* __restrict__ W1, const float* __restrict__ b1,
                  const float* __restrict__ b2v, const float* __restrict__ b3v,
                  const int* __restrict__ nearp, const int* __restrict__ farp,
                  float* __restrict__ out)
{
    extern __shared__ char smem[];
    const uint32_t smem_base = smem_u32(smem);
    const int tid = threadIdx.x;
    const int wid = tid >> 5;          // 0..7 = n-block owned by this warp
    const int lid = tid & 31;

    float*  b3s  = (float*)(smem + M_B3);
    float*  o1s  = (float*)(smem + M_O1);
    float*  d1s  = (float*)(smem + M_D1);
    float*  wt   = (float*)(smem + M_WT);
    float*  part = (float*)(smem + M_PART);
    float4* rend = (float4*)(smem + M_REND);

    if (tid < 4) b3s[tid] = b3v[tid];

    // ---- preload this warp's B fragments + W3 fragments into registers ----
    uint4 Bh[8], Bl[8];
    #pragma unroll
    for (int ks = 0; ks < 8; ks++) {
        Bh[ks] = g_bfh[(wid * 8 + ks) * 32 + lid];
        Bl[ks] = g_bfl[(wid * 8 + ks) * 32 + lid];
    }
    const uint2 W3h = g_w3h[wid * 32 + lid];
    const uint2 W3l = g_w3l[wid * 32 + lid];

    const int tq = lid & 3;
    const int q  = lid >> 2;
    const int c0 = wid * 16 + 2 * tq;
    const float bb0 = b2v[c0],     bb1 = b2v[c0 + 1];
    const float bb2 = b2v[c0 + 8], bb3 = b2v[c0 + 9];

    const float nearf = decode_scalar(nearp);
    const float farf  = decode_scalar(farp);
    const float delta = (farf - nearf) * (1.0f / (float)NS);

    // A ldmatrix lane address (validated mapping from R15/R16)
    const uint32_t a_lm = smem_base + M_A
        + (uint32_t)((lid & 15) * B_PITCH_B)
        + (uint32_t)((lid >> 4) * 16);

    // A-pack constants: thread packs sample s_pk (row), half hsel (32 uint32 cols)
    const int s_pk  = tid & 127;
    const int hsel  = tid >> 7;
    const float t_pk = fmaf((float)(s_pk & 63) + 0.5f, delta, nearf);
    uint4* arow = (uint4*)(smem + M_A + s_pk * B_PITCH_B + hsel * 128);

    __syncthreads();

    for (int tile = blockIdx.x; tile < NTILES; tile += gridDim.x) {
        // ---- layer-1 for 2 rays: o1 = o@W1 + b1, d1 = d@W1 (thread j = column) ----
        if (tid < HDIM) {
            int j = tid;
            float w0 = W1[j], w1v = W1[HDIM + j], w2v = W1[2 * HDIM + j], bb = b1[j];
            #pragma unroll
            for (int r = 0; r < 2; r++) {
                int ray = tile * 2 + r;
                float ox = origins[ray * 3 + 0], oy = origins[ray * 3 + 1], oz = origins[ray * 3 + 2];
                float dx = dirs[ray * 3 + 0],    dy = dirs[ray * 3 + 1],    dz = dirs[ray * 3 + 2];
                o1s[r * HDIM + j] = fmaf(ox, w0, fmaf(oy, w1v, fmaf(oz, w2v, bb)));
                d1s[r * HDIM + j] = fmaf(dx, w0, fmaf(dy, w1v, dz * w2v));
            }
        }
        __syncthreads();

        // ---- A-pack (each half packed once; STS.128 conflict-free) ----
        {
            const float2* o2 = (const float2*)(o1s + (s_pk >> 6) * HDIM);
            const float2* d2 = (const float2*)(d1s + (s_pk >> 6) * HDIM);
            #pragma unroll
            for (int i4 = 0; i4 < 8; i4++) {
                uint32_t v[4];
                #pragma unroll
                for (int j = 0; j < 4; j++) {
                    const int jj = hsel * 32 + i4 * 4 + j;
                    float2 o = o2[jj], d = d2[jj];
                    v[j] = pack2h(fmaxf(fmaf(t_pk, d.x, o.x), 0.0f),
                                  fmaxf(fmaf(t_pk, d.y, o.y), 0.0f));
                }
                arow[i4] = make_uint4(v[0], v[1], v[2], v[3]);
            }
        }
        __syncthreads();

        // ---- mainloop: warp sweeps 8 row-blocks x n16; fused layer-3 MMA epilogue ----
        for (int rb = 0; rb < 8; rb++) {
            const uint32_t a_rb = a_lm + (uint32_t)(rb * 16 * B_PITCH_B);
            // acc initialized with b2 (folds the bias; MMA always accumulates)
            float acc[8] = {bb0, bb1, bb0, bb1, bb2, bb3, bb2, bb3};

            #pragma unroll
            for (int ks = 0; ks < 8; ks++) {
                uint32_t a0, a1, a2, a3;
                LDSM_X4(a0, a1, a2, a3, a_rb + (uint32_t)(ks * 32));
                MMA16816(acc,     a0, a1, a2, a3, Bh[ks].x, Bh[ks].y);
                MMA16816(acc + 4, a0, a1, a2, a3, Bh[ks].z, Bh[ks].w);
                MMA16816(acc,     a0, a1, a2, a3, Bl[ks].x, Bl[ks].y);
                MMA16816(acc + 4, a0, a1, a2, a3, Bl[ks].z, Bl[ks].w);
            }

            // h2 = relu(acc); D-frag -> A-frag relayout is the identity
            uint32_t ah0 = pack2h(fmaxf(acc[0], 0.0f), fmaxf(acc[1], 0.0f));
            uint32_t ah1 = pack2h(fmaxf(acc[2], 0.0f), fmaxf(acc[3], 0.0f));
            uint32_t ah2 = pack2h(fmaxf(acc[4], 0.0f), fmaxf(acc[5], 0.0f));
            uint32_t ah3 = pack2h(fmaxf(acc[6], 0.0f), fmaxf(acc[7], 0.0f));

            // layer-3: [16 x 16k] @ [16k x 8n] (4 channels + 4 zero), W3 hi+lo chains
            float r2[4] = {0.0f, 0.0f, 0.0f, 0.0f};
            MMA16816(r2, ah0, ah1, ah2, ah3, W3h.x, W3h.y);
            MMA16816(r2, ah0, ah1, ah2, ah3, W3l.x, W3l.y);

            // lanes tq<2 hold the valid channel pairs (cols 2tq, 2tq+1)
            if (tq < 2) {
                const int row = rb * 16 + q;
                float2* s0 = (float2*)(rend + row * REND_S + wid);
                float2* s1 = (float2*)(rend + (row + 8) * REND_S + wid);
                s0[tq] = make_float2(r2[0], r2[1]);
                s1[tq] = make_float2(r2[2], r2[3]);
            }
        }
        __syncthreads();

        // ---- volume rendering: 2 rays, exact log-space scan (thread = sample) ----
        float cr = 0, cg = 0, cb = 0, sd = 0, x = 0;
        if (tid < 128) {
            float4 f = rend[tid * REND_S + 0];
            #pragma unroll
            for (int w = 1; w < 8; w++) {
                float4 g = rend[tid * REND_S + w];
                f.x += g.x; f.y += g.y; f.z += g.z; f.w += g.w;
            }
            cr = f.x + b3s[0]; cg = f.y + b3s[1]; cb = f.z + b3s[2];
            sd = (f.w + b3s[3]) * delta;

            x = sd;
            #pragma unroll
            for (int off = 1; off < 32; off <<= 1) {
                float v = __shfl_up_sync(0xffffffffu, x, off);
                if (lid >= off) x += v;
            }
            if (lid == 31) wt[wid] = x;
        }
        __syncthreads();
        if (tid < 128) {
            float pre = x - sd;
            if (wid & 1) pre += wt[wid & ~1];
            float w = __expf(-pre) - __expf(-(pre + sd));

            float wr = w * cr, wg = w * cg, wb = w * cb;
            #pragma unroll
            for (int off = 16; off > 0; off >>= 1) {
                wr += __shfl_down_sync(0xffffffffu, wr, off);
                wg += __shfl_down_sync(0xffffffffu, wg, off);
                wb += __shfl_down_sync(0xffffffffu, wb, off);
            }
            if (lid == 0) {
                float* p = part + wid * 4;
                p[0] = wr; p[1] = wg; p[2] = wb;
            }
        }
        __syncthreads();
        if (tid < 2) {
            const float* p0 = part + tid * 8;   // warps {2t, 2t+1}
            int ray = tile * 2 + tid;
            out[ray * 3 + 0] = p0[0] + p0[4];
            out[ray * 3 + 1] = p0[1] + p0[5];
            out[ray * 3 + 2] = p0[2] + p0[6];
        }
        // no trailing sync: o1s/A/rend/wt/part next written only after at least
        // one intervening __syncthreads in the next iteration.
    }
}

extern "C" void kernel_launch(void* const* d_in, const int* in_sizes, int n_in,
                              void* d_out, int out_size) {
    (void)in_sizes; (void)n_in; (void)out_size;
    const float* origins = (const float*)d_in[0];
    const float* dirs    = (const float*)d_in[1];
    const float* W1      = (const float*)d_in[2];
    const float* b1      = (const float*)d_in[3];
    const float* W2      = (const float*)d_in[4];
    const float* b2v     = (const float*)d_in[5];
    const float* W3      = (const float*)d_in[6];
    const float* b3v     = (const float*)d_in[7];
    const int*   nearp   = (const int*)d_in[8];
    const int*   farp    = (const int*)d_in[9];
    float* out = (float*)d_out;

    int sms = 0;
    cudaDeviceGetAttribute(&sms, cudaDevAttrMultiProcessorCount, 0);
    if (sms <= 0) sms = 148;

    cudaFuncSetAttribute(nerf_prep_kernel,
                         cudaFuncAttributeMaxDynamicSharedMemorySize, SMEM_PREP);
    nerf_prep_kernel<<<1, NTHREADS, SMEM_PREP>>>(W2, W3);

    cudaFuncSetAttribute(nerf_fused_kernel,
                         cudaFuncAttributeMaxDynamicSharedMemorySize, M_TOTAL);
    int grid = sms * 2;                 // persistent: 2 CTAs/SM
    if (grid > NTILES) grid = NTILES;
    nerf_fused_kernel<<<grid, NTHREADS, M_TOTAL>>>(
        origins, dirs, W1, b1, b2v, b3v, nearp, farp, out);
}